// round 1
// baseline (speedup 1.0000x reference)
#include <cuda_runtime.h>

#define NN 100000
#define EE 600000
#define HD 128
#define OD3 64
#define SA_STRIDE 132   // padded row stride for activation tiles (kills bank conflicts)

// Scratch (allocation-free rule: device globals)
__device__ float g_agg[(size_t)NN * HD];
__device__ float g_h[(size_t)NN * HD];
__device__ float g_deg[NN];

// ---------------- f32x2 helpers (packed fp32 FMA — PTX only) ----------------
__device__ __forceinline__ unsigned long long dup2(float a) {
    unsigned long long r;
    asm("mov.b64 %0, {%1, %1};" : "=l"(r) : "f"(a));
    return r;
}
__device__ __forceinline__ void fma2(unsigned long long& d, unsigned long long a, unsigned long long b) {
    asm("fma.rn.f32x2 %0, %1, %2, %0;" : "+l"(d) : "l"(a), "l"(b));
}
__device__ __forceinline__ float2 unpack2(unsigned long long v) {
    float2 r;
    asm("mov.b64 {%0, %1}, %2;" : "=f"(r.x), "=f"(r.y) : "l"(v));
    return r;
}

// ---------------- utility kernels ----------------
__global__ void k_zero(float4* p, int n4) {
    int i = blockIdx.x * blockDim.x + threadIdx.x;
    if (i < n4) p[i] = make_float4(0.f, 0.f, 0.f, 0.f);
}

__global__ void k_deg(const int* __restrict__ dst) {
    int e = blockIdx.x * blockDim.x + threadIdx.x;
    if (e < EE) atomicAdd(&g_deg[dst[e]], 1.0f);
}

// One warp per edge: lane c moves one float4 of the 128-dim row.
// Vector reduction (red.global.add.v4.f32, sm_90+) = 1 L2 atomic op per 16B.
__global__ void k_scatter(const float* __restrict__ xin,
                          const int* __restrict__ src,
                          const int* __restrict__ dst) {
    long long t = (long long)blockIdx.x * blockDim.x + threadIdx.x;
    int e = (int)(t >> 5);
    if (e >= EE) return;
    int c = (int)(t & 31);
    int s = __ldg(&src[e]);
    int d = __ldg(&dst[e]);
    float4 v = ((const float4*)(xin + (size_t)s * HD))[c];
    float* out = g_agg + (size_t)d * HD + (c << 2);
    asm volatile("red.global.add.v4.f32 [%0], {%1,%2,%3,%4};"
                 :: "l"(out), "f"(v.x), "f"(v.y), "f"(v.z), "f"(v.w) : "memory");
}

// ---------------- fused node kernel ----------------
// Per block: 64 nodes. Computes hout = act( BN( mean_agg @ Wl + bl + xin @ Wr ) )
// Wl/Wr staged in SMEM; thread tile = 4 nodes x (OUTD/16) cols, f32x2 accumulators.
template<int OUTD, bool BNRELU>
__global__ __launch_bounds__(256, 1)
void k_node(const float* __restrict__ xin,
            float* __restrict__ hout,
            const float* __restrict__ Wl, const float* __restrict__ bl,
            const float* __restrict__ Wr,
            const float* __restrict__ g, const float* __restrict__ be,
            const float* __restrict__ rm, const float* __restrict__ rv)
{
    extern __shared__ float sm[];
    float* sWl  = sm;                       // HD * OUTD
    float* sWr  = sWl + HD * OUTD;          // HD * OUTD
    float* sA   = sWr + HD * OUTD;          // 64 * SA_STRIDE
    float* sX   = sA + 64 * SA_STRIDE;      // 64 * SA_STRIDE
    float* sInv = sX + 64 * SA_STRIDE;      // 64

    const int t  = threadIdx.x;
    const int nb = blockIdx.x * 64;

    // stage weights
    const int w4 = HD * OUTD / 4;
    for (int i = t; i < w4; i += 256) {
        ((float4*)sWl)[i] = ((const float4*)Wl)[i];
        ((float4*)sWr)[i] = ((const float4*)Wr)[i];
    }
    if (t < 64) {
        int n = nb + t;
        float dg = (n < NN) ? g_deg[n] : 1.0f;
        sInv[t] = 1.0f / fmaxf(dg, 1.0f);
    }
    __syncthreads();

    // stage activations (mean-scaled agg + root features)
    for (int i = t; i < 64 * 32; i += 256) {
        int r = i >> 5, c4 = i & 31;
        int n = nb + r;
        float4 va = make_float4(0.f, 0.f, 0.f, 0.f);
        float4 vx = va;
        if (n < NN) {
            va = ((const float4*)(g_agg + (size_t)n * HD))[c4];
            float inv = sInv[r];
            va.x *= inv; va.y *= inv; va.z *= inv; va.w *= inv;
            vx = ((const float4*)(xin + (size_t)n * HD))[c4];
        }
        ((float4*)(sA + r * SA_STRIDE))[c4] = va;
        ((float4*)(sX + r * SA_STRIDE))[c4] = vx;
    }
    __syncthreads();

    constexpr int CPT = OUTD / 16;   // cols per thread (8 or 4)
    constexpr int P   = CPT / 2;     // f32x2 pairs per node (4 or 2)
    const int tx = t & 15, ty = t >> 4;
    const int j0 = tx * CPT;
    const int n0 = ty * 4;

    unsigned long long acc[4][P];
    #pragma unroll
    for (int p = 0; p < P; p++) {
        unsigned long long bp = *(const unsigned long long*)(bl + j0 + 2 * p);
        #pragma unroll
        for (int i = 0; i < 4; i++) acc[i][p] = bp;
    }

    #pragma unroll 2
    for (int k = 0; k < HD; k++) {
        unsigned long long wl[P], wr[P];
        const unsigned long long* pl = (const unsigned long long*)(sWl + k * OUTD + j0);
        const unsigned long long* pr = (const unsigned long long*)(sWr + k * OUTD + j0);
        #pragma unroll
        for (int p = 0; p < P; p++) { wl[p] = pl[p]; wr[p] = pr[p]; }
        #pragma unroll
        for (int i = 0; i < 4; i++) {
            unsigned long long aa = dup2(sA[(n0 + i) * SA_STRIDE + k]);
            unsigned long long xx = dup2(sX[(n0 + i) * SA_STRIDE + k]);
            #pragma unroll
            for (int p = 0; p < P; p++) {
                fma2(acc[i][p], wl[p], aa);
                fma2(acc[i][p], wr[p], xx);
            }
        }
    }

    float sc[CPT], sh[CPT];
    if (BNRELU) {
        #pragma unroll
        for (int c = 0; c < CPT; c++) {
            int j = j0 + c;
            float s = g[j] * rsqrtf(rv[j] + 1e-5f);
            sc[c] = s;
            sh[c] = be[j] - rm[j] * s;
        }
    }

    #pragma unroll
    for (int i = 0; i < 4; i++) {
        int n = nb + n0 + i;
        if (n >= NN) break;
        float* orow = hout + (size_t)n * OUTD + j0;
        #pragma unroll
        for (int p = 0; p < P; p++) {
            float2 v = unpack2(acc[i][p]);
            if (BNRELU) {
                v.x = fmaxf(v.x * sc[2 * p]     + sh[2 * p],     0.f);
                v.y = fmaxf(v.y * sc[2 * p + 1] + sh[2 * p + 1], 0.f);
            }
            *(float2*)(orow + 2 * p) = v;
        }
    }
}

// ---------------- launch ----------------
extern "C" void kernel_launch(void* const* d_in, const int* in_sizes, int n_in,
                              void* d_out, int out_size) {
    const float* x    = (const float*)d_in[0];
    const int*   ei   = (const int*)  d_in[1];
    const float* Wl1  = (const float*)d_in[2];
    const float* bl1  = (const float*)d_in[3];
    const float* Wr1  = (const float*)d_in[4];
    const float* g1   = (const float*)d_in[5];
    const float* be1  = (const float*)d_in[6];
    const float* rm1  = (const float*)d_in[7];
    const float* rv1  = (const float*)d_in[8];
    const float* Wl2  = (const float*)d_in[9];
    const float* bl2  = (const float*)d_in[10];
    const float* Wr2  = (const float*)d_in[11];
    const float* g2   = (const float*)d_in[12];
    const float* be2  = (const float*)d_in[13];
    const float* rm2  = (const float*)d_in[14];
    const float* rv2  = (const float*)d_in[15];
    const float* Wl3  = (const float*)d_in[16];
    const float* bl3  = (const float*)d_in[17];
    const float* Wr3  = (const float*)d_in[18];
    const int* src = ei;
    const int* dst = ei + EE;
    float* out = (float*)d_out;

    float *agg_p, *deg_p, *h_p;
    cudaGetSymbolAddress((void**)&agg_p, g_agg);
    cudaGetSymbolAddress((void**)&deg_p, g_deg);
    cudaGetSymbolAddress((void**)&h_p,   g_h);

    constexpr int SMEM12 = (HD * HD * 2 + 64 * SA_STRIDE * 2 + 64) * 4;   // 198912
    constexpr int SMEM3  = (HD * OD3 * 2 + 64 * SA_STRIDE * 2 + 64) * 4;  // 133376
    cudaFuncSetAttribute(k_node<HD, true>,  cudaFuncAttributeMaxDynamicSharedMemorySize, SMEM12);
    cudaFuncSetAttribute(k_node<OD3, false>, cudaFuncAttributeMaxDynamicSharedMemorySize, SMEM3);

    const int NB = (NN + 63) / 64;
    const int AGG4 = NN * HD / 4;
    const int DEG4 = NN / 4;
    const int SCAT_BLOCKS = (EE * 32 + 255) / 256;

    // degree (once)
    k_zero<<<(DEG4 + 255) / 256, 256>>>((float4*)deg_p, DEG4);
    k_deg<<<(EE + 255) / 256, 256>>>(dst);

    // layer 1
    k_zero<<<(AGG4 + 255) / 256, 256>>>((float4*)agg_p, AGG4);
    k_scatter<<<SCAT_BLOCKS, 256>>>(x, src, dst);
    k_node<HD, true><<<NB, 256, SMEM12>>>(x, h_p, Wl1, bl1, Wr1, g1, be1, rm1, rv1);

    // layer 2 (in place on g_h)
    k_zero<<<(AGG4 + 255) / 256, 256>>>((float4*)agg_p, AGG4);
    k_scatter<<<SCAT_BLOCKS, 256>>>(h_p, src, dst);
    k_node<HD, true><<<NB, 256, SMEM12>>>(h_p, h_p, Wl2, bl2, Wr2, g2, be2, rm2, rv2);

    // layer 3
    k_zero<<<(AGG4 + 255) / 256, 256>>>((float4*)agg_p, AGG4);
    k_scatter<<<SCAT_BLOCKS, 256>>>(h_p, src, dst);
    k_node<OD3, false><<<NB, 256, SMEM3>>>(h_p, out, Wl3, bl3, Wr3, bl3, bl3, bl3, bl3);
}

// round 2
// speedup vs baseline: 1.0181x; 1.0181x over previous
#include <cuda_runtime.h>

#define NN 100000
#define EE 600000
#define HD 128
#define OD3 64

typedef unsigned long long u64;

// ---- scratch (device globals: allocation-free rule) ----
__device__ float g_agg[(size_t)NN * HD];   // mean-aggregated features
__device__ float g_h[(size_t)NN * HD];     // hidden activations
__device__ int   g_cnt[NN];
__device__ int   g_rowstart[NN + 1];
__device__ int   g_cursor[NN];
__device__ int   g_csrc[EE];
__device__ u64   g_w2[HD * HD];            // interleaved (Wl, Wr) pairs

// ---- f32x2 helpers ----
__device__ __forceinline__ u64 pack2(float lo, float hi) {
    u64 r; asm("mov.b64 %0, {%1, %2};" : "=l"(r) : "f"(lo), "f"(hi)); return r;
}
__device__ __forceinline__ void fma2(u64& d, u64 a, u64 b) {
    asm("fma.rn.f32x2 %0, %1, %2, %0;" : "+l"(d) : "l"(a), "l"(b));
}
__device__ __forceinline__ float2 unpack2(u64 v) {
    float2 r; asm("mov.b64 {%0, %1}, %2;" : "=f"(r.x), "=f"(r.y) : "l"(v)); return r;
}

// ================= CSR build =================
__global__ void k_hist(const int* __restrict__ dst) {
    int e = blockIdx.x * blockDim.x + threadIdx.x;
    if (e < EE) atomicAdd(&g_cnt[dst[e]], 1);
}

__global__ void k_scan() {   // single block, 1024 threads
    __shared__ int sh[1024];
    const int tid = threadIdx.x;
    const int CH = (NN + 1023) / 1024;   // 98
    int base = tid * CH;
    int end  = min(base + CH, NN);
    int s = 0;
    for (int i = base; i < end; i++) s += g_cnt[i];
    sh[tid] = s;
    __syncthreads();
    for (int off = 1; off < 1024; off <<= 1) {
        int v = (tid >= off) ? sh[tid - off] : 0;
        __syncthreads();
        sh[tid] += v;
        __syncthreads();
    }
    int run = sh[tid] - s;   // exclusive offset for this chunk
    for (int i = base; i < end; i++) {
        g_rowstart[i] = run;
        g_cursor[i]   = run;
        run += g_cnt[i];
    }
    if (tid == 0) g_rowstart[NN] = EE;
}

__global__ void k_slot(const int* __restrict__ src, const int* __restrict__ dst) {
    int e = blockIdx.x * blockDim.x + threadIdx.x;
    if (e < EE) {
        int d = dst[e];
        int slot = atomicAdd(&g_cursor[d], 1);
        g_csrc[slot] = src[e];
    }
}

// ================= mean aggregation: warp per node =================
__global__ void k_gather(const float* __restrict__ xin) {
    int w = (blockIdx.x * blockDim.x + threadIdx.x) >> 5;
    if (w >= NN) return;
    int lane = threadIdx.x & 31;
    int b = g_rowstart[w], e2 = g_rowstart[w + 1];
    float4 a0 = make_float4(0.f, 0.f, 0.f, 0.f);
    float4 a1 = make_float4(0.f, 0.f, 0.f, 0.f);
    int j = b;
    for (; j + 1 < e2; j += 2) {
        int s0 = __ldg(&g_csrc[j]);
        int s1 = __ldg(&g_csrc[j + 1]);
        float4 v0 = __ldg((const float4*)(xin + (size_t)s0 * HD) + lane);
        float4 v1 = __ldg((const float4*)(xin + (size_t)s1 * HD) + lane);
        a0.x += v0.x; a0.y += v0.y; a0.z += v0.z; a0.w += v0.w;
        a1.x += v1.x; a1.y += v1.y; a1.z += v1.z; a1.w += v1.w;
    }
    if (j < e2) {
        int s0 = __ldg(&g_csrc[j]);
        float4 v0 = __ldg((const float4*)(xin + (size_t)s0 * HD) + lane);
        a0.x += v0.x; a0.y += v0.y; a0.z += v0.z; a0.w += v0.w;
    }
    float inv = 1.0f / fmaxf((float)(e2 - b), 1.0f);
    float4 r;
    r.x = (a0.x + a1.x) * inv; r.y = (a0.y + a1.y) * inv;
    r.z = (a0.z + a1.z) * inv; r.w = (a0.w + a1.w) * inv;
    ((float4*)(g_agg + (size_t)w * HD))[lane] = r;
}

// ================= weight interleave: g_w2[k*OUTD+j] = (Wl, Wr) =================
__global__ void k_wpack(const float* __restrict__ Wl, const float* __restrict__ Wr, int n) {
    int t = blockIdx.x * blockDim.x + threadIdx.x;
    if (t < n) g_w2[t] = pack2(Wl[t], Wr[t]);
}

// ================= fused node GEMM =================
// 512 threads = 16 warps. Block covers 64 nodes.
// Warp w owns cols [w*C, w*C+C). Lane covers nodes {lane, lane+32}.
// acc[n][c] is f32x2: lo = bias + sum agg*Wl, hi = sum x*Wr. out = lo+hi.
// Acts in SMEM as interleaved (agg,x) u64, row stride 129 u64 (conflict-free).
// Weights streamed warp-uniform from g_w2 (L1/L2), zero SMEM cost.
template<int OUTD, bool BN>
__global__ __launch_bounds__(512, 1)
void k_node(const float* __restrict__ xin, float* __restrict__ hout,
            const float* __restrict__ bl,
            const float* __restrict__ g, const float* __restrict__ be,
            const float* __restrict__ rm, const float* __restrict__ rv)
{
    extern __shared__ u64 sAX[];   // [64][129]
    const int t  = threadIdx.x;
    const int nb = blockIdx.x * 64;

    // ---- stage interleaved acts: warp per node-row, coalesced ----
    for (int idx = t; idx < 64 * 32; idx += 512) {
        int node = idx >> 5, c4 = idx & 31;
        int n = nb + node;
        float4 a  = make_float4(0.f, 0.f, 0.f, 0.f);
        float4 xv = a;
        if (n < NN) {
            a  = __ldg((const float4*)(g_agg + (size_t)n * HD) + c4);
            xv = __ldg((const float4*)(xin   + (size_t)n * HD) + c4);
        }
        u64* dp = sAX + node * 129 + c4 * 4;
        dp[0] = pack2(a.x, xv.x);
        dp[1] = pack2(a.y, xv.y);
        dp[2] = pack2(a.z, xv.z);
        dp[3] = pack2(a.w, xv.w);
    }
    __syncthreads();

    constexpr int C = OUTD / 16;       // 8 (OUTD=128) or 4 (OUTD=64)
    const int wid  = t >> 5;
    const int lane = t & 31;
    const int j0   = wid * C;

    u64 acc[2][C];
    #pragma unroll
    for (int c = 0; c < C; c++) {
        u64 bi = pack2(__ldg(&bl[j0 + c]), 0.f);
        acc[0][c] = bi; acc[1][c] = bi;
    }

    const u64* __restrict__ wbase = g_w2 + j0;
    const u64* __restrict__ a0p = sAX + (size_t)lane * 129;
    const u64* __restrict__ a1p = sAX + (size_t)(lane + 32) * 129;

    #pragma unroll 2
    for (int k = 0; k < HD; k++) {
        u64 w[C];
        const ulonglong2* wr2 = (const ulonglong2*)(wbase + (size_t)k * OUTD);
        #pragma unroll
        for (int i = 0; i < C / 2; i++) {
            ulonglong2 v = __ldg(wr2 + i);
            w[2 * i] = v.x; w[2 * i + 1] = v.y;
        }
        u64 a0 = a0p[k];
        u64 a1 = a1p[k];
        #pragma unroll
        for (int c = 0; c < C; c++) {
            fma2(acc[0][c], a0, w[c]);
            fma2(acc[1][c], a1, w[c]);
        }
    }

    // ---- epilogue: combine halves, BN+ReLU, store ----
    float sc[C], sh[C];
    if (BN) {
        #pragma unroll
        for (int c = 0; c < C; c++) {
            int j = j0 + c;
            float s = __ldg(&g[j]) * rsqrtf(__ldg(&rv[j]) + 1e-5f);
            sc[c] = s;
            sh[c] = __ldg(&be[j]) - __ldg(&rm[j]) * s;
        }
    }
    #pragma unroll
    for (int i = 0; i < 2; i++) {
        int n = nb + lane + 32 * i;
        if (n >= NN) continue;
        float v[C];
        #pragma unroll
        for (int c = 0; c < C; c++) {
            float2 p = unpack2(acc[i][c]);
            float r = p.x + p.y;
            if (BN) r = fmaxf(r * sc[c] + sh[c], 0.f);
            v[c] = r;
        }
        float* orow = hout + (size_t)n * OUTD + j0;
        #pragma unroll
        for (int c = 0; c < C; c += 4)
            *(float4*)(orow + c) = make_float4(v[c], v[c + 1], v[c + 2], v[c + 3]);
    }
}

// ================= launch =================
extern "C" void kernel_launch(void* const* d_in, const int* in_sizes, int n_in,
                              void* d_out, int out_size) {
    const float* x    = (const float*)d_in[0];
    const int*   ei   = (const int*)  d_in[1];
    const float* Wl1  = (const float*)d_in[2];
    const float* bl1  = (const float*)d_in[3];
    const float* Wr1  = (const float*)d_in[4];
    const float* g1   = (const float*)d_in[5];
    const float* be1  = (const float*)d_in[6];
    const float* rm1  = (const float*)d_in[7];
    const float* rv1  = (const float*)d_in[8];
    const float* Wl2  = (const float*)d_in[9];
    const float* bl2  = (const float*)d_in[10];
    const float* Wr2  = (const float*)d_in[11];
    const float* g2   = (const float*)d_in[12];
    const float* be2  = (const float*)d_in[13];
    const float* rm2  = (const float*)d_in[14];
    const float* rv2  = (const float*)d_in[15];
    const float* Wl3  = (const float*)d_in[16];
    const float* bl3  = (const float*)d_in[17];
    const float* Wr3  = (const float*)d_in[18];
    const int* src = ei;
    const int* dst = ei + EE;
    float* out = (float*)d_out;

    float *h_p;
    int   *cnt_p;
    cudaGetSymbolAddress((void**)&h_p,   g_h);
    cudaGetSymbolAddress((void**)&cnt_p, g_cnt);

    constexpr int SMEM = 64 * 129 * 8;   // 66048
    cudaFuncSetAttribute(k_node<HD, true>,   cudaFuncAttributeMaxDynamicSharedMemorySize, SMEM);
    cudaFuncSetAttribute(k_node<OD3, false>, cudaFuncAttributeMaxDynamicSharedMemorySize, SMEM);

    const int EB = (EE + 255) / 256;
    const int GB = (NN * 32 + 255) / 256;
    const int NB = (NN + 63) / 64;       // 1563

    // CSR build (once)
    cudaMemsetAsync(cnt_p, 0, NN * sizeof(int));
    k_hist<<<EB, 256>>>(dst);
    k_scan<<<1, 1024>>>();
    k_slot<<<EB, 256>>>(src, dst);

    // layer 1
    k_gather<<<GB, 256>>>(x);
    k_wpack<<<(HD * HD + 255) / 256, 256>>>(Wl1, Wr1, HD * HD);
    k_node<HD, true><<<NB, 512, SMEM>>>(x, h_p, bl1, g1, be1, rm1, rv1);

    // layer 2 (in place on g_h: each block reads only its own staged rows)
    k_gather<<<GB, 256>>>(h_p);
    k_wpack<<<(HD * HD + 255) / 256, 256>>>(Wl2, Wr2, HD * HD);
    k_node<HD, true><<<NB, 512, SMEM>>>(h_p, h_p, bl2, g2, be2, rm2, rv2);

    // layer 3
    k_gather<<<GB, 256>>>(h_p);
    k_wpack<<<(HD * OD3 + 255) / 256, 256>>>(Wl3, Wr3, HD * OD3);
    k_node<OD3, false><<<NB, 512, SMEM>>>(h_p, out, bl3, bl3, bl3, bl3, bl3);
}

// round 4
// speedup vs baseline: 2.0273x; 1.9911x over previous
#include <cuda_runtime.h>
#include <cuda_bf16.h>

#define NN 100000
#define EE 600000
#define HD 128
#define OD3 64
#define KSB 272          // SMEM/global row stride in bytes for bf16 K=128 rows (128*2 + 16 pad)
#define KSE 136          // same in bf16 elements

typedef unsigned long long u64;
typedef unsigned int u32;

// ---------------- scratch (device globals: allocation-free rule) ----------------
__device__ float g_agg[(size_t)NN * HD];
__device__ float g_h[(size_t)NN * HD];
__device__ int   g_cnt[NN];
__device__ int   g_rowstart[NN + 1];
__device__ int   g_cursor[NN];
__device__ int   g_csrc[EE];
// padded bf16 weight images, [chunk(Wl/Wr)][split(hi/lo)][n*KSE + k]  (B = W^T)
__device__ __align__(16) __nv_bfloat16 g_bimg[2][2][HD * KSE];

// ---------------- PTX helpers (all baseline sm_80+ instructions) ----------------
__device__ __forceinline__ u32 smem_u32(const void* p) {
    u32 a;
    asm("{ .reg .u64 t; cvta.to.shared.u64 t, %1; cvt.u32.u64 %0, t; }" : "=r"(a) : "l"(p));
    return a;
}
__device__ __forceinline__ void ldsm4(u32* r, u32 addr) {
    asm volatile("ldmatrix.sync.aligned.m8n8.x4.shared.b16 {%0,%1,%2,%3}, [%4];"
                 : "=r"(r[0]), "=r"(r[1]), "=r"(r[2]), "=r"(r[3]) : "r"(addr));
}
__device__ __forceinline__ void ldsm2(u32* r, u32 addr) {
    asm volatile("ldmatrix.sync.aligned.m8n8.x2.shared.b16 {%0,%1}, [%2];"
                 : "=r"(r[0]), "=r"(r[1]) : "r"(addr));
}
__device__ __forceinline__ void mma16816(float* c, const u32* a, const u32* b) {
    asm volatile("mma.sync.aligned.m16n8k16.row.col.f32.bf16.bf16.f32 "
                 "{%0,%1,%2,%3}, {%4,%5,%6,%7}, {%8,%9}, {%0,%1,%2,%3};"
                 : "+f"(c[0]), "+f"(c[1]), "+f"(c[2]), "+f"(c[3])
                 : "r"(a[0]), "r"(a[1]), "r"(a[2]), "r"(a[3]), "r"(b[0]), "r"(b[1]));
}

// ================= CSR build =================
__global__ void k_hist(const int* __restrict__ dst) {
    int e = blockIdx.x * blockDim.x + threadIdx.x;
    if (e < EE) atomicAdd(&g_cnt[dst[e]], 1);
}

__global__ void k_scan() {   // single block, 1024 threads
    __shared__ int sh[1024];
    const int tid = threadIdx.x;
    const int CH = (NN + 1023) / 1024;
    int base = tid * CH;
    int end  = min(base + CH, NN);
    int s = 0;
    for (int i = base; i < end; i++) s += g_cnt[i];
    sh[tid] = s;
    __syncthreads();
    for (int off = 1; off < 1024; off <<= 1) {
        int v = (tid >= off) ? sh[tid - off] : 0;
        __syncthreads();
        sh[tid] += v;
        __syncthreads();
    }
    int run = sh[tid] - s;
    for (int i = base; i < end; i++) {
        g_rowstart[i] = run;
        g_cursor[i]   = run;
        run += g_cnt[i];
    }
    if (tid == 0) g_rowstart[NN] = EE;
}

__global__ void k_slot(const int* __restrict__ src, const int* __restrict__ dst) {
    int e = blockIdx.x * blockDim.x + threadIdx.x;
    if (e < EE) {
        int d = dst[e];
        int slot = atomicAdd(&g_cursor[d], 1);
        g_csrc[slot] = src[e];
    }
}

// ================= mean aggregation: warp per node =================
__global__ void k_gather(const float* __restrict__ xin) {
    int w = (blockIdx.x * blockDim.x + threadIdx.x) >> 5;
    if (w >= NN) return;
    int lane = threadIdx.x & 31;
    int b = g_rowstart[w], e2 = g_rowstart[w + 1];
    float4 a0 = make_float4(0.f, 0.f, 0.f, 0.f);
    float4 a1 = make_float4(0.f, 0.f, 0.f, 0.f);
    int j = b;
    for (; j + 1 < e2; j += 2) {
        int s0 = __ldg(&g_csrc[j]);
        int s1 = __ldg(&g_csrc[j + 1]);
        float4 v0 = __ldg((const float4*)(xin + (size_t)s0 * HD) + lane);
        float4 v1 = __ldg((const float4*)(xin + (size_t)s1 * HD) + lane);
        a0.x += v0.x; a0.y += v0.y; a0.z += v0.z; a0.w += v0.w;
        a1.x += v1.x; a1.y += v1.y; a1.z += v1.z; a1.w += v1.w;
    }
    if (j < e2) {
        int s0 = __ldg(&g_csrc[j]);
        float4 v0 = __ldg((const float4*)(xin + (size_t)s0 * HD) + lane);
        a0.x += v0.x; a0.y += v0.y; a0.z += v0.z; a0.w += v0.w;
    }
    float inv = 1.0f / fmaxf((float)(e2 - b), 1.0f);
    float4 r;
    r.x = (a0.x + a1.x) * inv; r.y = (a0.y + a1.y) * inv;
    r.z = (a0.z + a1.z) * inv; r.w = (a0.w + a1.w) * inv;
    ((float4*)(g_agg + (size_t)w * HD))[lane] = r;
}

// ================= weight prepack: B = W^T, bf16 hi/lo, padded rows =================
template<int N_>
__global__ void k_bpack(const float* __restrict__ Wl, const float* __restrict__ Wr) {
    int t = blockIdx.x * blockDim.x + threadIdx.x;
    if (t >= 2 * HD * N_) return;
    int chunk = t / (HD * N_);
    int rem = t - chunk * HD * N_;
    int k = rem / N_, n = rem % N_;
    float v = __ldg((chunk ? Wr : Wl) + k * N_ + n);
    __nv_bfloat16 hi = __float2bfloat16(v);
    __nv_bfloat16 lo = __float2bfloat16(v - __bfloat162float(hi));
    g_bimg[chunk][0][n * KSE + k] = hi;
    g_bimg[chunk][1][n * KSE + k] = lo;
}

// ================= fused node kernel: mma.sync bf16-split GEMM =================
// Block: 256 nodes, 512 threads = 16 warps x 16 rows. K=256 as two 128-chunks
// (agg@Wl, x@Wr), fp32 register accumulators. D = Ahi*Bhi + Ahi*Blo + Alo*Bhi.
template<int N_, bool RELU>
__global__ __launch_bounds__(512, 1)
void k_node(const float* __restrict__ xin, float* __restrict__ hout,
            const float* __restrict__ bl, const float* __restrict__ g,
            const float* __restrict__ be, const float* __restrict__ rm,
            const float* __restrict__ rv)
{
    extern __shared__ char smem[];
    constexpr int SM_A1 = 0;
    constexpr int SM_A2 = SM_A1 + 256 * KSB;
    constexpr int SM_B1 = SM_A2 + 256 * KSB;
    constexpr int SM_B2 = SM_B1 + N_ * KSB;
    constexpr int SM_SC = SM_B2 + N_ * KSB;
    constexpr int SM_SH = SM_SC + 512;
    constexpr int NT = N_ / 8;           // n8 tiles (16 or 8)

    const int tid  = threadIdx.x;
    const int wid  = tid >> 5;
    const int lane = tid & 31;
    const int nb   = blockIdx.x * 256;
    const u32 sb   = smem_u32(smem);

    // BN scale/shift (bias folded)
    if (tid < N_) {
        float s, sh;
        if (RELU) {
            float sc_ = __ldg(&g[tid]) * rsqrtf(__ldg(&rv[tid]) + 1e-5f);
            s  = sc_;
            sh = (__ldg(&bl[tid]) - __ldg(&rm[tid])) * sc_ + __ldg(&be[tid]);
        } else {
            s  = 1.0f;
            sh = __ldg(&bl[tid]);
        }
        *(float*)(smem + SM_SC + tid * 4) = s;
        *(float*)(smem + SM_SH + tid * 4) = sh;
    }

    // ldmatrix lane addresses
    const u32 aOff = (u32)((wid * 16 + (lane & 15)) * KSB + (lane >> 4) * 16);
    const u32 aad1 = sb + SM_A1 + aOff;
    const u32 aad2 = sb + SM_A2 + aOff;
    const u32 bOff = (u32)((lane & 7) * KSB + ((lane >> 3) & 1) * 16);
    const u32 bad1 = sb + SM_B1 + bOff;
    const u32 bad2 = sb + SM_B2 + bOff;

    float acc[NT][4];
    #pragma unroll
    for (int j = 0; j < NT; j++) {
        acc[j][0] = 0.f; acc[j][1] = 0.f; acc[j][2] = 0.f; acc[j][3] = 0.f;
    }

    for (int chunk = 0; chunk < 2; chunk++) {
        // ---- stage A (fp32 -> bf16 hi/lo) ----
        const float* asrc = chunk ? xin : g_agg;
        for (int idx = tid; idx < 256 * 32; idx += 512) {
            int r = idx >> 5, c4 = idx & 31;
            int n = nb + r;
            float4 v = make_float4(0.f, 0.f, 0.f, 0.f);
            if (n < NN) v = __ldg((const float4*)(asrc + (size_t)n * HD) + c4);
            __nv_bfloat162 h0 = __floats2bfloat162_rn(v.x, v.y);
            __nv_bfloat162 h1 = __floats2bfloat162_rn(v.z, v.w);
            float2 f0 = __bfloat1622float2(h0);
            float2 f1 = __bfloat1622float2(h1);
            __nv_bfloat162 l0 = __floats2bfloat162_rn(v.x - f0.x, v.y - f0.y);
            __nv_bfloat162 l1 = __floats2bfloat162_rn(v.z - f1.x, v.w - f1.y);
            u64 hi64 = (u64)(*(u32*)&h0) | ((u64)(*(u32*)&h1) << 32);
            u64 lo64 = (u64)(*(u32*)&l0) | ((u64)(*(u32*)&l1) << 32);
            *(u64*)(smem + SM_A1 + r * KSB + c4 * 8) = hi64;
            *(u64*)(smem + SM_A2 + r * KSB + c4 * 8) = lo64;
        }
        // ---- stage B: raw copy of padded pre-packed images ----
        {
            const float4* b1s = (const float4*)&g_bimg[chunk][0][0];
            const float4* b2s = (const float4*)&g_bimg[chunk][1][0];
            for (int i = tid; i < N_ * KSB / 16; i += 512) {
                ((float4*)(smem + SM_B1))[i] = __ldg(b1s + i);
                ((float4*)(smem + SM_B2))[i] = __ldg(b2s + i);
            }
        }
        __syncthreads();

        // ---- MMA mainloop ----
        #pragma unroll
        for (int k16 = 0; k16 < 8; k16++) {
            u32 ah[4], al[4];
            ldsm4(ah, aad1 + k16 * 32);
            ldsm4(al, aad2 + k16 * 32);
            #pragma unroll
            for (int j = 0; j < NT; j++) {
                u32 bh[2], blo[2];
                ldsm2(bh, bad1 + j * 8 * KSB + k16 * 32);
                mma16816(acc[j], ah, bh);
                mma16816(acc[j], al, bh);
                ldsm2(blo, bad2 + j * 8 * KSB + k16 * 32);
                mma16816(acc[j], ah, blo);
            }
        }
        __syncthreads();   // done reading SMEM before restage
    }

    // ---- epilogue: BN/bias/ReLU, direct stores ----
    const int r0 = wid * 16 + (lane >> 2);
    const int n0 = nb + r0;
    const int n1 = n0 + 8;
    const int cbase = (lane & 3) * 2;
    #pragma unroll
    for (int j = 0; j < NT; j++) {
        int c = j * 8 + cbase;
        float s0 = *(const float*)(smem + SM_SC + c * 4);
        float s1 = *(const float*)(smem + SM_SC + (c + 1) * 4);
        float h0 = *(const float*)(smem + SM_SH + c * 4);
        float h1 = *(const float*)(smem + SM_SH + (c + 1) * 4);
        if (n0 < NN) {
            float2 o;
            o.x = acc[j][0] * s0 + h0;
            o.y = acc[j][1] * s1 + h1;
            if (RELU) { o.x = fmaxf(o.x, 0.f); o.y = fmaxf(o.y, 0.f); }
            *(float2*)(hout + (size_t)n0 * N_ + c) = o;
        }
        if (n1 < NN) {
            float2 o;
            o.x = acc[j][2] * s0 + h0;
            o.y = acc[j][3] * s1 + h1;
            if (RELU) { o.x = fmaxf(o.x, 0.f); o.y = fmaxf(o.y, 0.f); }
            *(float2*)(hout + (size_t)n1 * N_ + c) = o;
        }
    }
}

// ================= launch =================
extern "C" void kernel_launch(void* const* d_in, const int* in_sizes, int n_in,
                              void* d_out, int out_size) {
    const float* x    = (const float*)d_in[0];
    const int*   ei   = (const int*)  d_in[1];
    const float* Wl1  = (const float*)d_in[2];
    const float* bl1  = (const float*)d_in[3];
    const float* Wr1  = (const float*)d_in[4];
    const float* g1   = (const float*)d_in[5];
    const float* be1  = (const float*)d_in[6];
    const float* rm1  = (const float*)d_in[7];
    const float* rv1  = (const float*)d_in[8];
    const float* Wl2  = (const float*)d_in[9];
    const float* bl2  = (const float*)d_in[10];
    const float* Wr2  = (const float*)d_in[11];
    const float* g2   = (const float*)d_in[12];
    const float* be2  = (const float*)d_in[13];
    const float* rm2  = (const float*)d_in[14];
    const float* rv2  = (const float*)d_in[15];
    const float* Wl3  = (const float*)d_in[16];
    const float* bl3  = (const float*)d_in[17];
    const float* Wr3  = (const float*)d_in[18];
    const int* src = ei;
    const int* dst = ei + EE;
    float* out = (float*)d_out;

    float* h_p;
    int*   cnt_p;
    cudaGetSymbolAddress((void**)&h_p,   g_h);
    cudaGetSymbolAddress((void**)&cnt_p, g_cnt);

    constexpr int SMEM12 = 256 * KSB * 2 + HD  * KSB * 2 + 1024;   // 209920
    constexpr int SMEM3  = 256 * KSB * 2 + OD3 * KSB * 2 + 1024;   // 175104
    cudaFuncSetAttribute(k_node<HD, true>,   cudaFuncAttributeMaxDynamicSharedMemorySize, SMEM12);
    cudaFuncSetAttribute(k_node<OD3, false>, cudaFuncAttributeMaxDynamicSharedMemorySize, SMEM3);

    const int EB = (EE + 255) / 256;
    const int GB = (NN * 32 + 255) / 256;
    const int NB = (NN + 255) / 256;   // 391

    // CSR build (once)
    cudaMemsetAsync(cnt_p, 0, NN * sizeof(int));
    k_hist<<<EB, 256>>>(dst);
    k_scan<<<1, 1024>>>();
    k_slot<<<EB, 256>>>(src, dst);

    // layer 1
    k_bpack<HD><<<(2 * HD * HD + 255) / 256, 256>>>(Wl1, Wr1);
    k_gather<<<GB, 256>>>(x);
    k_node<HD, true><<<NB, 512, SMEM12>>>(x, h_p, bl1, g1, be1, rm1, rv1);

    // layer 2 (in place on g_h: each block touches only its own rows)
    k_bpack<HD><<<(2 * HD * HD + 255) / 256, 256>>>(Wl2, Wr2);
    k_gather<<<GB, 256>>>(h_p);
    k_node<HD, true><<<NB, 512, SMEM12>>>(h_p, h_p, bl2, g2, be2, rm2, rv2);

    // layer 3
    k_bpack<OD3><<<(2 * HD * OD3 + 255) / 256, 256>>>(Wl3, Wr3);
    k_gather<<<GB, 256>>>(h_p);
    k_node<OD3, false><<<NB, 512, SMEM3>>>(h_p, out, bl3, bl3, bl3, bl3, bl3);
}

// round 5
// speedup vs baseline: 2.0703x; 1.0212x over previous
#include <cuda_runtime.h>
#include <cuda_bf16.h>

#define NN 100000
#define EE 600000
#define HD 128
#define OD3 64
#define KSB 144          // row stride bytes for 64 bf16 cols (+8 elem pad)
#define KSE 72           // same in elements

typedef unsigned long long u64;
typedef unsigned int u32;

// ---------------- scratch (device globals) ----------------
__device__ float g_agg[(size_t)NN * HD];
__device__ float g_h[(size_t)NN * HD];
__device__ int   g_cnt[NN];
__device__ int   g_rowstart[NN + 1];
__device__ int   g_cursor[NN];
__device__ int   g_csrc[EE];
// padded bf16 weight images per 64-wide K chunk: [chunk 0..3][split hi/lo][n*KSE + kk]
// chunks 0,1 = Wl k[0:64),[64:128); chunks 2,3 = Wr. B = W^T.
__device__ __align__(16) __nv_bfloat16 g_bimg[4][2][HD * KSE];

// ---------------- PTX helpers ----------------
__device__ __forceinline__ u32 smem_u32(const void* p) {
    u32 a;
    asm("{ .reg .u64 t; cvta.to.shared.u64 t, %1; cvt.u32.u64 %0, t; }" : "=r"(a) : "l"(p));
    return a;
}
__device__ __forceinline__ void ldsm4(u32* r, u32 addr) {
    asm volatile("ldmatrix.sync.aligned.m8n8.x4.shared.b16 {%0,%1,%2,%3}, [%4];"
                 : "=r"(r[0]), "=r"(r[1]), "=r"(r[2]), "=r"(r[3]) : "r"(addr));
}
__device__ __forceinline__ void ldsm2(u32* r, u32 addr) {
    asm volatile("ldmatrix.sync.aligned.m8n8.x2.shared.b16 {%0,%1}, [%2];"
                 : "=r"(r[0]), "=r"(r[1]) : "r"(addr));
}
__device__ __forceinline__ void mma16816(float* c, const u32* a, const u32* b) {
    asm volatile("mma.sync.aligned.m16n8k16.row.col.f32.bf16.bf16.f32 "
                 "{%0,%1,%2,%3}, {%4,%5,%6,%7}, {%8,%9}, {%0,%1,%2,%3};"
                 : "+f"(c[0]), "+f"(c[1]), "+f"(c[2]), "+f"(c[3])
                 : "r"(a[0]), "r"(a[1]), "r"(a[2]), "r"(a[3]), "r"(b[0]), "r"(b[1]));
}

// ================= CSR build =================
__global__ void k_hist(const int* __restrict__ dst) {
    int e = blockIdx.x * blockDim.x + threadIdx.x;
    if (e < EE) atomicAdd(&g_cnt[dst[e]], 1);
}

__global__ void k_scan() {
    __shared__ int sh[1024];
    const int tid = threadIdx.x;
    const int CH = (NN + 1023) / 1024;
    int base = tid * CH;
    int end  = min(base + CH, NN);
    int s = 0;
    for (int i = base; i < end; i++) s += g_cnt[i];
    sh[tid] = s;
    __syncthreads();
    for (int off = 1; off < 1024; off <<= 1) {
        int v = (tid >= off) ? sh[tid - off] : 0;
        __syncthreads();
        sh[tid] += v;
        __syncthreads();
    }
    int run = sh[tid] - s;
    for (int i = base; i < end; i++) {
        g_rowstart[i] = run;
        g_cursor[i]   = run;
        run += g_cnt[i];
    }
    if (tid == 0) g_rowstart[NN] = EE;
}

__global__ void k_slot(const int* __restrict__ src, const int* __restrict__ dst) {
    int e = blockIdx.x * blockDim.x + threadIdx.x;
    if (e < EE) {
        int d = dst[e];
        int slot = atomicAdd(&g_cursor[d], 1);
        g_csrc[slot] = src[e];
    }
}

// ================= mean aggregation: warp per node =================
__global__ void k_gather(const float* __restrict__ xin) {
    int w = (blockIdx.x * blockDim.x + threadIdx.x) >> 5;
    if (w >= NN) return;
    int lane = threadIdx.x & 31;
    int b = g_rowstart[w], e2 = g_rowstart[w + 1];
    float4 a0 = make_float4(0.f, 0.f, 0.f, 0.f);
    float4 a1 = make_float4(0.f, 0.f, 0.f, 0.f);
    int j = b;
    for (; j + 1 < e2; j += 2) {
        int s0 = __ldg(&g_csrc[j]);
        int s1 = __ldg(&g_csrc[j + 1]);
        float4 v0 = __ldg((const float4*)(xin + (size_t)s0 * HD) + lane);
        float4 v1 = __ldg((const float4*)(xin + (size_t)s1 * HD) + lane);
        a0.x += v0.x; a0.y += v0.y; a0.z += v0.z; a0.w += v0.w;
        a1.x += v1.x; a1.y += v1.y; a1.z += v1.z; a1.w += v1.w;
    }
    if (j < e2) {
        int s0 = __ldg(&g_csrc[j]);
        float4 v0 = __ldg((const float4*)(xin + (size_t)s0 * HD) + lane);
        a0.x += v0.x; a0.y += v0.y; a0.z += v0.z; a0.w += v0.w;
    }
    float inv = 1.0f / fmaxf((float)(e2 - b), 1.0f);
    float4 r;
    r.x = (a0.x + a1.x) * inv; r.y = (a0.y + a1.y) * inv;
    r.z = (a0.z + a1.z) * inv; r.w = (a0.w + a1.w) * inv;
    ((float4*)(g_agg + (size_t)w * HD))[lane] = r;
}

// ================= weight prepack: 4 K-chunks, B = W^T, bf16 hi/lo =================
template<int N_>
__global__ void k_bpack(const float* __restrict__ Wl, const float* __restrict__ Wr) {
    int t = blockIdx.x * blockDim.x + threadIdx.x;
    if (t >= 4 * 64 * N_) return;
    int chunk = t / (64 * N_);
    int rem = t - chunk * 64 * N_;
    int kk = rem / N_, n = rem % N_;
    const float* W = (chunk < 2) ? Wl : Wr;
    int gk = (chunk & 1) * 64 + kk;
    float v = __ldg(W + gk * N_ + n);
    __nv_bfloat16 hi = __float2bfloat16(v);
    __nv_bfloat16 lo = __float2bfloat16(v - __bfloat162float(hi));
    g_bimg[chunk][0][n * KSE + kk] = hi;
    g_bimg[chunk][1][n * KSE + kk] = lo;
}

// ================= fused node kernel: mma.sync bf16-split GEMM =================
// Block: 128 nodes, 256 threads = 8 warps in a 4x2 grid; warp tile 32 rows x 64 cols.
// K = 256 processed as 4 chunks of 64 (agg|x), fp32 accumulators persist.
// D = Ahi*Bhi + Alo*Bhi + Ahi*Blo. 2 blocks/SM for stage/MMA overlap.
template<int N_, bool RELU>
__global__ __launch_bounds__(256, 2)
void k_node(const float* __restrict__ xin, float* __restrict__ hout,
            const float* __restrict__ bl, const float* __restrict__ g,
            const float* __restrict__ be, const float* __restrict__ rm,
            const float* __restrict__ rv)
{
    extern __shared__ char smem[];
    constexpr int SM_A1 = 0;                       // 128*144 = 18432
    constexpr int SM_A2 = SM_A1 + 128 * KSB;
    constexpr int SM_B1 = SM_A2 + 128 * KSB;       // N_*144
    constexpr int SM_B2 = SM_B1 + N_ * KSB;
    constexpr int SM_SC = SM_B2 + N_ * KSB;
    constexpr int SM_SH = SM_SC + 512;
    constexpr int NJ = N_ / 8 / 2;                 // j tiles per warp (8 for N=128, 4 for N=64)

    const int tid  = threadIdx.x;
    const int wid  = tid >> 5;
    const int lane = tid & 31;
    const int wr   = (wid >> 1) * 32;              // warp row base (0,32,64,96)
    const int wc   = (wid & 1) * (N_ / 2);         // warp col base
    const int nb   = blockIdx.x * 128;
    const u32 sb   = smem_u32(smem);

    // BN scale/shift (bias folded)
    if (tid < N_) {
        float s, sh;
        if (RELU) {
            float sc_ = __ldg(&g[tid]) * rsqrtf(__ldg(&rv[tid]) + 1e-5f);
            s  = sc_;
            sh = (__ldg(&bl[tid]) - __ldg(&rm[tid])) * sc_ + __ldg(&be[tid]);
        } else {
            s  = 1.0f;
            sh = __ldg(&bl[tid]);
        }
        *(float*)(smem + SM_SC + tid * 4) = s;
        *(float*)(smem + SM_SH + tid * 4) = sh;
    }

    // ldmatrix lane addresses
    const u32 aOff = (u32)((wr + (lane & 15)) * KSB + (lane >> 4) * 16);
    const u32 aad1 = sb + SM_A1 + aOff;
    const u32 aad2 = sb + SM_A2 + aOff;
    const u32 bOff = (u32)((wc + (lane & 7)) * KSB + ((lane >> 3) & 1) * 16);
    const u32 bad1 = sb + SM_B1 + bOff;
    const u32 bad2 = sb + SM_B2 + bOff;

    float acc[2][NJ][4];
    #pragma unroll
    for (int m = 0; m < 2; m++)
        #pragma unroll
        for (int j = 0; j < NJ; j++) {
            acc[m][j][0] = 0.f; acc[m][j][1] = 0.f;
            acc[m][j][2] = 0.f; acc[m][j][3] = 0.f;
        }

    #pragma unroll
    for (int chunk = 0; chunk < 4; chunk++) {
        // ---- stage A: 128 rows x 64 cols fp32 -> bf16 hi/lo ----
        const float* asrc = (chunk < 2) ? g_agg : xin;
        const int colofs = (chunk & 1) * 16;   // in float4 units
        for (int idx = tid; idx < 128 * 16; idx += 256) {
            int r = idx >> 4, c4 = idx & 15;
            int n = nb + r;
            float4 v = make_float4(0.f, 0.f, 0.f, 0.f);
            if (n < NN) v = __ldg((const float4*)(asrc + (size_t)n * HD) + colofs + c4);
            __nv_bfloat162 h0 = __floats2bfloat162_rn(v.x, v.y);
            __nv_bfloat162 h1 = __floats2bfloat162_rn(v.z, v.w);
            float2 f0 = __bfloat1622float2(h0);
            float2 f1 = __bfloat1622float2(h1);
            __nv_bfloat162 l0 = __floats2bfloat162_rn(v.x - f0.x, v.y - f0.y);
            __nv_bfloat162 l1 = __floats2bfloat162_rn(v.z - f1.x, v.w - f1.y);
            u64 hi64 = (u64)(*(u32*)&h0) | ((u64)(*(u32*)&h1) << 32);
            u64 lo64 = (u64)(*(u32*)&l0) | ((u64)(*(u32*)&l1) << 32);
            *(u64*)(smem + SM_A1 + r * KSB + c4 * 8) = hi64;
            *(u64*)(smem + SM_A2 + r * KSB + c4 * 8) = lo64;
        }
        // ---- stage B: raw copy of pre-packed padded images ----
        {
            const float4* b1s = (const float4*)&g_bimg[chunk][0][0];
            const float4* b2s = (const float4*)&g_bimg[chunk][1][0];
            for (int i = tid; i < N_ * KSB / 16; i += 256) {
                ((float4*)(smem + SM_B1))[i] = __ldg(b1s + i);
                ((float4*)(smem + SM_B2))[i] = __ldg(b2s + i);
            }
        }
        __syncthreads();

        // ---- MMA: 4 k16 steps ----
        #pragma unroll
        for (int k16 = 0; k16 < 4; k16++) {
            u32 ah0[4], ah1[4], al0[4], al1[4];
            ldsm4(ah0, aad1 + k16 * 32);
            ldsm4(ah1, aad1 + 16 * KSB + k16 * 32);
            ldsm4(al0, aad2 + k16 * 32);
            ldsm4(al1, aad2 + 16 * KSB + k16 * 32);
            #pragma unroll
            for (int j = 0; j < NJ; j++) {
                u32 bh[2], blo[2];
                ldsm2(bh,  bad1 + j * 8 * KSB + k16 * 32);
                mma16816(acc[0][j], ah0, bh);
                mma16816(acc[1][j], ah1, bh);
                mma16816(acc[0][j], al0, bh);
                mma16816(acc[1][j], al1, bh);
                ldsm2(blo, bad2 + j * 8 * KSB + k16 * 32);
                mma16816(acc[0][j], ah0, blo);
                mma16816(acc[1][j], ah1, blo);
            }
        }
        __syncthreads();   // finished reading before restage
    }

    // ---- epilogue: BN/bias/ReLU, float2 stores ----
    const int cb = (lane & 3) * 2;
    #pragma unroll
    for (int m = 0; m < 2; m++) {
        int n0 = nb + wr + m * 16 + (lane >> 2);
        int n1 = n0 + 8;
        #pragma unroll
        for (int j = 0; j < NJ; j++) {
            int c = wc + j * 8 + cb;
            float s0 = *(const float*)(smem + SM_SC + c * 4);
            float s1 = *(const float*)(smem + SM_SC + (c + 1) * 4);
            float h0 = *(const float*)(smem + SM_SH + c * 4);
            float h1 = *(const float*)(smem + SM_SH + (c + 1) * 4);
            if (n0 < NN) {
                float2 o;
                o.x = acc[m][j][0] * s0 + h0;
                o.y = acc[m][j][1] * s1 + h1;
                if (RELU) { o.x = fmaxf(o.x, 0.f); o.y = fmaxf(o.y, 0.f); }
                *(float2*)(hout + (size_t)n0 * N_ + c) = o;
            }
            if (n1 < NN) {
                float2 o;
                o.x = acc[m][j][2] * s0 + h0;
                o.y = acc[m][j][3] * s1 + h1;
                if (RELU) { o.x = fmaxf(o.x, 0.f); o.y = fmaxf(o.y, 0.f); }
                *(float2*)(hout + (size_t)n1 * N_ + c) = o;
            }
        }
    }
}

// ================= launch =================
extern "C" void kernel_launch(void* const* d_in, const int* in_sizes, int n_in,
                              void* d_out, int out_size) {
    const float* x    = (const float*)d_in[0];
    const int*   ei   = (const int*)  d_in[1];
    const float* Wl1  = (const float*)d_in[2];
    const float* bl1  = (const float*)d_in[3];
    const float* Wr1  = (const float*)d_in[4];
    const float* g1   = (const float*)d_in[5];
    const float* be1  = (const float*)d_in[6];
    const float* rm1  = (const float*)d_in[7];
    const float* rv1  = (const float*)d_in[8];
    const float* Wl2  = (const float*)d_in[9];
    const float* bl2  = (const float*)d_in[10];
    const float* Wr2  = (const float*)d_in[11];
    const float* g2   = (const float*)d_in[12];
    const float* be2  = (const float*)d_in[13];
    const float* rm2  = (const float*)d_in[14];
    const float* rv2  = (const float*)d_in[15];
    const float* Wl3  = (const float*)d_in[16];
    const float* bl3  = (const float*)d_in[17];
    const float* Wr3  = (const float*)d_in[18];
    const int* src = ei;
    const int* dst = ei + EE;
    float* out = (float*)d_out;

    float* h_p;
    int*   cnt_p;
    cudaGetSymbolAddress((void**)&h_p,   g_h);
    cudaGetSymbolAddress((void**)&cnt_p, g_cnt);

    constexpr int SMEM12 = 128 * KSB * 2 + HD  * KSB * 2 + 1024;   // 74752
    constexpr int SMEM3  = 128 * KSB * 2 + OD3 * KSB * 2 + 1024;   // 56320
    cudaFuncSetAttribute(k_node<HD, true>,   cudaFuncAttributeMaxDynamicSharedMemorySize, SMEM12);
    cudaFuncSetAttribute(k_node<OD3, false>, cudaFuncAttributeMaxDynamicSharedMemorySize, SMEM3);

    const int EB = (EE + 255) / 256;
    const int GB = (NN * 32 + 255) / 256;
    const int NB = (NN + 127) / 128;   // 782

    // CSR build (once)
    cudaMemsetAsync(cnt_p, 0, NN * sizeof(int));
    k_hist<<<EB, 256>>>(dst);
    k_scan<<<1, 1024>>>();
    k_slot<<<EB, 256>>>(src, dst);

    // layer 1
    k_bpack<HD><<<(4 * 64 * HD + 255) / 256, 256>>>(Wl1, Wr1);
    k_gather<<<GB, 256>>>(x);
    k_node<HD, true><<<NB, 256, SMEM12>>>(x, h_p, bl1, g1, be1, rm1, rv1);

    // layer 2 (in place on g_h: each block touches only its own rows)
    k_bpack<HD><<<(4 * 64 * HD + 255) / 256, 256>>>(Wl2, Wr2);
    k_gather<<<GB, 256>>>(h_p);
    k_node<HD, true><<<NB, 256, SMEM12>>>(h_p, h_p, bl2, g2, be2, rm2, rv2);

    // layer 3
    k_bpack<OD3><<<(4 * 64 * OD3 + 255) / 256, 256>>>(Wl3, Wr3);
    k_gather<<<GB, 256>>>(h_p);
    k_node<OD3, false><<<NB, 256, SMEM3>>>(h_p, out, bl3, bl3, bl3, bl3, bl3);
}